// round 6
// baseline (speedup 1.0000x reference)
#include <cuda_runtime.h>

typedef unsigned long long u64;

__device__ __forceinline__ u64 pk2(float lo, float hi){
  u64 r; asm("mov.b64 %0, {%1, %2};" : "=l"(r) : "f"(lo), "f"(hi)); return r;
}
__device__ __forceinline__ void upk2(u64 v, float& lo, float& hi){
  asm("mov.b64 {%0, %1}, %2;" : "=f"(lo), "=f"(hi) : "l"(v));
}
__device__ __forceinline__ u64 ffma2(u64 a, u64 b, u64 c){
  u64 r; asm("fma.rn.f32x2 %0, %1, %2, %3;" : "=l"(r) : "l"(a), "l"(b), "l"(c)); return r;
}
__device__ __forceinline__ u64 fmul2(u64 a, u64 b){
  u64 r; asm("mul.rn.f32x2 %0, %1, %2;" : "=l"(r) : "l"(a), "l"(b)); return r;
}
__device__ __forceinline__ u64 fadd2(u64 a, u64 b){
  u64 r; asm("add.rn.f32x2 %0, %1, %2;" : "=l"(r) : "l"(a), "l"(b)); return r;
}

#define NWARP 8
#define GRID_BLOCKS 456   // 152 SMs * 3 resident blocks

// Fused PillarVFE, persistent warps, TWO pillars per warp-iteration (ILP).
//   pre[n,o] = A[o]x + B[o]y + C[o]z + D[o]w + bias_p[o]
//   out[o]   = max( max_{n<npts} pre, npts<32 ? bn_bias[o] : -inf, 0 )
// Max over UNBIASED dots in the loop; bias added once (max-monotone).
// Lanes >= npts stage point 0 (max-idempotent) -> both pillars run the quad
// loop branch-free to tmax = max(trips1, trips2).
__global__ __launch_bounds__(256, 3) void pillar_vfe_kernel(
    const float4* __restrict__ voxels,   // [P,32] xyzw
    const float*  __restrict__ W,        // [64,9]
    const float*  __restrict__ gamma,
    const float*  __restrict__ beta,
    const float*  __restrict__ rmean,
    const float*  __restrict__ rvar,
    const int*    __restrict__ vnum,     // [P]
    const int*    __restrict__ vcoords,  // [P,4] (b,z,y,x)
    float*        __restrict__ out,      // [P,64]
    int P)
{
  __shared__ float cf[10][64];                            // folded coefficients
  __shared__ u64   nct[7][32];                            // per-lane packed: ncf4..8, bb2, rbb2
  __shared__ __align__(16) float shp[NWARP][2][2][4][32]; // [warp][buf][pillar][row][pt]

  int tid = threadIdx.x;
  if (tid < 64) {
    int o = tid;
    float s = gamma[o] / sqrtf(rvar[o] + 1e-3f);
    const float* w = W + o * 9;
    float w0=w[0], w1=w[1], w2=w[2], w3=w[3], w4=w[4], w5=w[5], w6=w[6], w7=w[7], w8=w[8];
    float S0 = w0 + w7, S1 = w1 + w8;   // xc / yc channels duplicated (c0+c7, c1+c8)
    cf[0][o] = s * (S0 + w4);           // * x
    cf[1][o] = s * (S1 + w5);           // * y
    cf[2][o] = s * (w2 + w6);           // * z
    cf[3][o] = s * w3;                  // * intensity
    cf[4][o] = s * S0;                  // * cx
    cf[5][o] = s * S1;                  // * cy
    cf[6][o] = s * w4;                  // * mx
    cf[7][o] = s * w5;                  // * my
    cf[8][o] = s * w6;                  // * mz
    cf[9][o] = beta[o] - rmean[o] * s;  // BN bias (= masked-point pre-activation)
  }
  __syncthreads();
  if (tid < 32) {
    int l = tid, a = 2 * l, b = 2 * l + 1;
    nct[0][l] = pk2(-cf[4][a], -cf[4][b]);
    nct[1][l] = pk2(-cf[5][a], -cf[5][b]);
    nct[2][l] = pk2(-cf[6][a], -cf[6][b]);
    nct[3][l] = pk2(-cf[7][a], -cf[7][b]);
    nct[4][l] = pk2(-cf[8][a], -cf[8][b]);
    nct[5][l] = pk2(cf[9][a], cf[9][b]);
    nct[6][l] = pk2(fmaxf(cf[9][a], 0.0f), fmaxf(cf[9][b], 0.0f));
  }
  __syncthreads();

  int lane = tid & 31;
  int wrp  = tid >> 5;
  int NWt  = gridDim.x * NWARP;
  int npair = (P + 1) >> 1;
  int pair = blockIdx.x * NWARP + wrp;
  if (pair >= npair) return;

  // Loop coefficients in registers (duplicated per channel pair).
  int c0 = 2 * lane, c1 = 2 * lane + 1;
  u64 pA0 = pk2(cf[0][c0], cf[0][c0]), pA1 = pk2(cf[0][c1], cf[0][c1]);
  u64 pB0 = pk2(cf[1][c0], cf[1][c0]), pB1 = pk2(cf[1][c1], cf[1][c1]);
  u64 pC0 = pk2(cf[2][c0], cf[2][c0]), pC1 = pk2(cf[2][c1], cf[2][c1]);
  u64 pD0 = pk2(cf[3][c0], cf[3][c0]), pD1 = pk2(cf[3][c1], cf[3][c1]);

  // ---- Load first pair.
  int pa = 2 * pair, pb = pa + 1;
  float4 vA = voxels[(size_t)pa * 32 + lane];
  int   npA = vnum[pa];
  int2 cyxA = *reinterpret_cast<const int2*>(vcoords + (size_t)pa * 4 + 2);
  bool hasB = (pb < P);
  float4 vB = vA; int npB = npA; int2 cyxB = cyxA;
  if (hasB) {
    vB   = voxels[(size_t)pb * 32 + lane];
    npB  = vnum[pb];
    cyxB = *reinterpret_cast<const int2*>(vcoords + (size_t)pb * 4 + 2);
  }

  int buf = 0;
  for (;;) {
    // ---- Prefetch next pair (hides DRAM latency behind compute).
    int pairn = pair + NWt;
    bool more = (pairn < npair);
    float4 vNA, vNB; int npNA = 1, npNB = 1;
    int2 cyxNA = make_int2(0, 0), cyxNB = make_int2(0, 0);
    bool hasNB = false;
    if (more) {
      int pna = 2 * pairn, pnb = pna + 1;
      vNA   = voxels[(size_t)pna * 32 + lane];
      npNA  = vnum[pna];
      cyxNA = *reinterpret_cast<const int2*>(vcoords + (size_t)pna * 4 + 2);
      hasNB = (pnb < P);
      vNB = vNA; npNB = npNA; cyxNB = cyxNA;
      if (hasNB) {
        vNB   = voxels[(size_t)pnb * 32 + lane];
        npNB  = vnum[pnb];
        cyxNB = *reinterpret_cast<const int2*>(vcoords + (size_t)pnb * 4 + 2);
      }
    }

    // ---- Interleaved butterflies (two independent chains hide SHFL latency).
    u64 sxyA = pk2(vA.x, vA.y); float szA = vA.z;
    u64 sxyB = pk2(vB.x, vB.y); float szB = vB.z;
    #pragma unroll
    for (int off = 16; off; off >>= 1) {
      float la, ha, lb, hb;
      upk2(sxyA, la, ha);
      upk2(sxyB, lb, hb);
      float la2 = __shfl_xor_sync(0xffffffffu, la, off);
      float lb2 = __shfl_xor_sync(0xffffffffu, lb, off);
      float ha2 = __shfl_xor_sync(0xffffffffu, ha, off);
      float hb2 = __shfl_xor_sync(0xffffffffu, hb, off);
      float za2 = __shfl_xor_sync(0xffffffffu, szA, off);
      float zb2 = __shfl_xor_sync(0xffffffffu, szB, off);
      sxyA = fadd2(sxyA, pk2(la2, ha2));
      sxyB = fadd2(sxyB, pk2(lb2, hb2));
      szA += za2;
      szB += zb2;
    }
    float rnA = __fdividef(1.0f, (float)npA);
    float rnB = __fdividef(1.0f, (float)npB);
    float sxA, syA, sxB, syB;
    upk2(sxyA, sxA, syA);
    upk2(sxyB, sxB, syB);
    float mxA = sxA * rnA, myA = syA * rnA, mzA = szA * rnA;
    float mxB = sxB * rnB, myB = syB * rnB, mzB = szB * rnB;

    // ---- Stage both pillars (pad invalid lanes with point 0).
    float xa0 = __shfl_sync(0xffffffffu, vA.x, 0);
    float ya0 = __shfl_sync(0xffffffffu, vA.y, 0);
    float za0 = __shfl_sync(0xffffffffu, vA.z, 0);
    float wa0 = __shfl_sync(0xffffffffu, vA.w, 0);
    float xb0 = __shfl_sync(0xffffffffu, vB.x, 0);
    float yb0 = __shfl_sync(0xffffffffu, vB.y, 0);
    float zb0 = __shfl_sync(0xffffffffu, vB.z, 0);
    float wb0 = __shfl_sync(0xffffffffu, vB.w, 0);
    bool vaOK = (lane < npA), vbOK = (lane < npB);
    float* sA = &shp[wrp][buf][0][0][0];
    float* sB = &shp[wrp][buf][1][0][0];
    sA[lane]      = vaOK ? vA.x : xa0;
    sA[32 + lane] = vaOK ? vA.y : ya0;
    sA[64 + lane] = vaOK ? vA.z : za0;
    sA[96 + lane] = vaOK ? vA.w : wa0;
    sB[lane]      = vbOK ? vB.x : xb0;
    sB[32 + lane] = vbOK ? vB.y : yb0;
    sB[64 + lane] = vbOK ? vB.z : zb0;
    sB[96 + lane] = vbOK ? vB.w : wb0;
    __syncwarp();

    // ---- Quad loop: branch-free to tmax; padded slots are max-idempotent.
    const ulonglong2* rqA = reinterpret_cast<const ulonglong2*>(sA);
    const ulonglong2* rqB = reinterpret_cast<const ulonglong2*>(sB);
    int tA = (npA + 3) >> 2, tB = (npB + 3) >> 2;
    int tmax = tA > tB ? tA : tB;        // 1..8
    float m0A = -3.4e38f, m1A = -3.4e38f;
    float m0B = -3.4e38f, m1B = -3.4e38f;
    #pragma unroll
    for (int q = 0; q < 8; q++) {
      if (q >= tmax) break;
      {
        ulonglong2 X = rqA[q],      Y  = rqA[8 + q];
        ulonglong2 Z = rqA[16 + q], Wv = rqA[24 + q];
        u64 s01 = fmul2(pA0, X.x);  s01 = ffma2(pB0, Y.x, s01);
        u64 s23 = fmul2(pA0, X.y);  s23 = ffma2(pB0, Y.y, s23);
        u64 r01 = fmul2(pA1, X.x);  r01 = ffma2(pB1, Y.x, r01);
        u64 r23 = fmul2(pA1, X.y);  r23 = ffma2(pB1, Y.y, r23);
        s01 = ffma2(pC0, Z.x, s01); s01 = ffma2(pD0, Wv.x, s01);
        s23 = ffma2(pC0, Z.y, s23); s23 = ffma2(pD0, Wv.y, s23);
        r01 = ffma2(pC1, Z.x, r01); r01 = ffma2(pD1, Wv.x, r01);
        r23 = ffma2(pC1, Z.y, r23); r23 = ffma2(pD1, Wv.y, r23);
        float a, b, c, d;
        upk2(s01, a, b); upk2(s23, c, d);
        m0A = fmaxf(m0A, fmaxf(fmaxf(a, b), fmaxf(c, d)));
        upk2(r01, a, b); upk2(r23, c, d);
        m1A = fmaxf(m1A, fmaxf(fmaxf(a, b), fmaxf(c, d)));
      }
      {
        ulonglong2 X = rqB[q],      Y  = rqB[8 + q];
        ulonglong2 Z = rqB[16 + q], Wv = rqB[24 + q];
        u64 s01 = fmul2(pA0, X.x);  s01 = ffma2(pB0, Y.x, s01);
        u64 s23 = fmul2(pA0, X.y);  s23 = ffma2(pB0, Y.y, s23);
        u64 r01 = fmul2(pA1, X.x);  r01 = ffma2(pB1, Y.x, r01);
        u64 r23 = fmul2(pA1, X.y);  r23 = ffma2(pB1, Y.y, r23);
        s01 = ffma2(pC0, Z.x, s01); s01 = ffma2(pD0, Wv.x, s01);
        s23 = ffma2(pC0, Z.y, s23); s23 = ffma2(pD0, Wv.y, s23);
        r01 = ffma2(pC1, Z.x, r01); r01 = ffma2(pD1, Wv.x, r01);
        r23 = ffma2(pC1, Z.y, r23); r23 = ffma2(pD1, Wv.y, r23);
        float a, b, c, d;
        upk2(s01, a, b); upk2(s23, c, d);
        m0B = fmaxf(m0B, fmaxf(fmaxf(a, b), fmaxf(c, d)));
        upk2(r01, a, b); upk2(r23, c, d);
        m1B = fmaxf(m1B, fmaxf(fmaxf(a, b), fmaxf(c, d)));
      }
    }

    // ---- Bias + epilogue (coefficients from per-lane smem table).
    u64 n0 = nct[0][lane], n1 = nct[1][lane], n2 = nct[2][lane];
    u64 n3 = nct[3][lane], n4 = nct[4][lane], bb2 = nct[5][lane];
    u64 rbb2 = nct[6][lane];
    float rbb0, rbb1;
    upk2(rbb2, rbb0, rbb1);
    {
      float cx = fmaf((float)cyxA.y, 0.16f, 0.08f);
      float cy = fmaf((float)cyxA.x, 0.16f, -39.6f);
      u64 bias2 = ffma2(pk2(cx, cx), n0, bb2);
      bias2 = ffma2(pk2(cy, cy), n1, bias2);
      bias2 = ffma2(pk2(mxA, mxA), n2, bias2);
      bias2 = ffma2(pk2(myA, myA), n3, bias2);
      bias2 = ffma2(pk2(mzA, mzA), n4, bias2);
      u64 t2 = fadd2(pk2(m0A, m1A), bias2);
      float t0, t1;
      upk2(t2, t0, t1);
      float g0 = (npA < 32) ? rbb0 : 0.0f;
      float g1 = (npA < 32) ? rbb1 : 0.0f;
      reinterpret_cast<float2*>(out)[(size_t)pa * 32 + lane] =
          make_float2(fmaxf(t0, g0), fmaxf(t1, g1));
    }
    if (hasB) {
      float cx = fmaf((float)cyxB.y, 0.16f, 0.08f);
      float cy = fmaf((float)cyxB.x, 0.16f, -39.6f);
      u64 bias2 = ffma2(pk2(cx, cx), n0, bb2);
      bias2 = ffma2(pk2(cy, cy), n1, bias2);
      bias2 = ffma2(pk2(mxB, mxB), n2, bias2);
      bias2 = ffma2(pk2(myB, myB), n3, bias2);
      bias2 = ffma2(pk2(mzB, mzB), n4, bias2);
      u64 t2 = fadd2(pk2(m0B, m1B), bias2);
      float t0, t1;
      upk2(t2, t0, t1);
      float g0 = (npB < 32) ? rbb0 : 0.0f;
      float g1 = (npB < 32) ? rbb1 : 0.0f;
      reinterpret_cast<float2*>(out)[(size_t)pb * 32 + lane] =
          make_float2(fmaxf(t0, g0), fmaxf(t1, g1));
    }

    if (!more) break;
    pair = pairn;
    pa = 2 * pair; pb = pa + 1;
    vA = vNA; npA = npNA; cyxA = cyxNA;
    vB = vNB; npB = npNB; cyxB = cyxNB;
    hasB = hasNB;
    buf ^= 1;
  }
}

extern "C" void kernel_launch(void* const* d_in, const int* in_sizes, int n_in,
                              void* d_out, int out_size) {
  const float4* voxels = (const float4*)d_in[0];
  const float*  W      = (const float*)d_in[1];
  const float*  gamma  = (const float*)d_in[2];
  const float*  beta   = (const float*)d_in[3];
  const float*  rmean  = (const float*)d_in[4];
  const float*  rvar   = (const float*)d_in[5];
  const int*    vnum   = (const int*)d_in[6];
  const int*    vcrd   = (const int*)d_in[7];
  float* out = (float*)d_out;

  int P = in_sizes[6];
  int npair = (P + 1) / 2;
  int needed = (npair + NWARP - 1) / NWARP;
  int blocks = needed < GRID_BLOCKS ? needed : GRID_BLOCKS;
  pillar_vfe_kernel<<<blocks, 256>>>(voxels, W, gamma, beta, rmean, rvar,
                                     vnum, vcrd, out, P);
}

// round 7
// speedup vs baseline: 1.0860x; 1.0860x over previous
#include <cuda_runtime.h>

typedef unsigned long long u64;

__device__ __forceinline__ u64 pk2(float lo, float hi){
  u64 r; asm("mov.b64 %0, {%1, %2};" : "=l"(r) : "f"(lo), "f"(hi)); return r;
}
__device__ __forceinline__ u64 ffma2(u64 a, u64 b, u64 c){
  u64 r; asm("fma.rn.f32x2 %0, %1, %2, %3;" : "=l"(r) : "l"(a), "l"(b), "l"(c)); return r;
}
__device__ __forceinline__ u64 fmul2(u64 a, u64 b){
  u64 r; asm("mul.rn.f32x2 %0, %1, %2;" : "=l"(r) : "l"(a), "l"(b)); return r;
}
__device__ __forceinline__ u64 fadd2(u64 a, u64 b){
  u64 r; asm("add.rn.f32x2 %0, %1, %2;" : "=l"(r) : "l"(a), "l"(b)); return r;
}
// Register-pair alias views (no asm movs; let ptxas fold).
__device__ __forceinline__ float lo2(u64 v){ return reinterpret_cast<float2*>(&v)->x; }
__device__ __forceinline__ float hi2(u64 v){ return reinterpret_cast<float2*>(&v)->y; }

#define NWARP 8
#define GRID_BLOCKS 608   // 152 SMs * 4 resident blocks

// Fused PillarVFE, persistent warps, one pillar per warp-iteration.
//   pre[n,o] = A[o]x + B[o]y + C[o]z + D[o]w + bias_p[o]
//   out[o]   = max( max_{n<npts} pre, npts<32 ? bn_bias[o] : -inf, 0 )
// Max over UNBIASED dots in the loop; per-pillar bias added once (max-monotone).
// Lanes >= npts stage point 0 (max-idempotent) -> no scalar tail.
// Lane owns channels (2*lane, 2*lane+1) -> one st.global.v2 per pillar.
__global__ __launch_bounds__(256, 4) void pillar_vfe_kernel(
    const float4* __restrict__ voxels,   // [P,32] xyzw
    const float*  __restrict__ W,        // [64,9]
    const float*  __restrict__ gamma,
    const float*  __restrict__ beta,
    const float*  __restrict__ rmean,
    const float*  __restrict__ rvar,
    const int*    __restrict__ vnum,     // [P]
    const int*    __restrict__ vcoords,  // [P,4] (b,z,y,x)
    float*        __restrict__ out,      // [P,64]
    int P)
{
  __shared__ float cf[10][64];                         // folded coefficients
  __shared__ __align__(16) float shp[NWARP][2][4][32]; // double-buffered staging

  int tid = threadIdx.x;
  if (tid < 64) {
    int o = tid;
    float s = gamma[o] / sqrtf(rvar[o] + 1e-3f);
    const float* w = W + o * 9;
    float w0=w[0], w1=w[1], w2=w[2], w3=w[3], w4=w[4], w5=w[5], w6=w[6], w7=w[7], w8=w[8];
    float S0 = w0 + w7, S1 = w1 + w8;   // xc / yc channels duplicated (c0+c7, c1+c8)
    cf[0][o] = s * (S0 + w4);           // * x
    cf[1][o] = s * (S1 + w5);           // * y
    cf[2][o] = s * (w2 + w6);           // * z
    cf[3][o] = s * w3;                  // * intensity
    cf[4][o] = s * S0;                  // * cx
    cf[5][o] = s * S1;                  // * cy
    cf[6][o] = s * w4;                  // * mx
    cf[7][o] = s * w5;                  // * my
    cf[8][o] = s * w6;                  // * mz
    cf[9][o] = beta[o] - rmean[o] * s;  // BN bias (= masked-point pre-activation)
  }
  __syncthreads();

  int lane = tid & 31;
  int wrp  = tid >> 5;
  int NWt  = gridDim.x * NWARP;
  int p    = blockIdx.x * NWARP + wrp;
  if (p >= P) return;

  // ---- Hoisted per-warp constants. Lane owns channels c0=2*lane, c1=2*lane+1.
  int c0 = 2 * lane, c1 = 2 * lane + 1;
  // Packed point-pair loop coefficients (value duplicated in both halves).
  u64 pA0 = pk2(cf[0][c0], cf[0][c0]), pA1 = pk2(cf[0][c1], cf[0][c1]);
  u64 pB0 = pk2(cf[1][c0], cf[1][c0]), pB1 = pk2(cf[1][c1], cf[1][c1]);
  u64 pC0 = pk2(cf[2][c0], cf[2][c0]), pC1 = pk2(cf[2][c1], cf[2][c1]);
  u64 pD0 = pk2(cf[3][c0], cf[3][c0]), pD1 = pk2(cf[3][c1], cf[3][c1]);
  // Scalar (negated) bias coefficients: bias = bb - cx*cf4 - cy*cf5 - m.*cf678
  float n4a = -cf[4][c0], n4b = -cf[4][c1];
  float n5a = -cf[5][c0], n5b = -cf[5][c1];
  float n6a = -cf[6][c0], n6b = -cf[6][c1];
  float n7a = -cf[7][c0], n7b = -cf[7][c1];
  float n8a = -cf[8][c0], n8b = -cf[8][c1];
  float bb0 = cf[9][c0], bb1 = cf[9][c1];
  float rbb0 = fmaxf(bb0, 0.0f), rbb1 = fmaxf(bb1, 0.0f);

  float* sbase = &shp[wrp][0][0][0];
  int bufoff = 0;                        // toggles 0 / 128 floats

  // ---- Current pillar state.
  float4 v  = voxels[(size_t)p * 32 + lane];                               // LDG.128
  int np    = vnum[p];
  int2 cyx  = *reinterpret_cast<const int2*>(vcoords + (size_t)p * 4 + 2); // (y,x)

  for (;;) {
    // Prefetch next pillar (hides DRAM latency behind this pillar's compute).
    int pn = p + NWt;
    bool more = (pn < P);
    float4 vN; int npN = 0; int2 cyxN = make_int2(0, 0);
    if (more) {
      vN   = voxels[(size_t)pn * 32 + lane];
      npN  = vnum[pn];
      cyxN = *reinterpret_cast<const int2*>(vcoords + (size_t)pn * 4 + 2);
    }

    // Mean sums over ALL 32 points (reference sums unmasked).
    // 64-bit shuffle butterfly on packed (x,y): 2 SHFL + 1 fadd2 / level.
    u64  sxy = pk2(v.x, v.y);
    float sz = v.z;
    #pragma unroll
    for (int off = 16; off; off >>= 1) {
      u64 o2 = __shfl_xor_sync(0xffffffffu, sxy, off);
      float oz = __shfl_xor_sync(0xffffffffu, sz, off);
      sxy = fadd2(sxy, o2);
      sz += oz;
    }

    // Stage transposed points; pad invalid lanes with point 0 (max-idempotent).
    float x0 = __shfl_sync(0xffffffffu, v.x, 0);
    float y0 = __shfl_sync(0xffffffffu, v.y, 0);
    float z0 = __shfl_sync(0xffffffffu, v.z, 0);
    float w0 = __shfl_sync(0xffffffffu, v.w, 0);
    bool valid = (lane < np);
    float* sb = sbase + bufoff;
    sb[lane]      = valid ? v.x : x0;
    sb[32 + lane] = valid ? v.y : y0;
    sb[64 + lane] = valid ? v.z : z0;
    sb[96 + lane] = valid ? v.w : w0;
    __syncwarp();

    // Quad loop: 4 points / trip, fully unrolled, immediate LDS offsets.
    const ulonglong2* rq = reinterpret_cast<const ulonglong2*>(sb);
    float m0 = -3.4e38f, m1 = -3.4e38f;
    int trips = (np + 3) >> 2;            // 1..8
    #pragma unroll
    for (int q = 0; q < 8; q++) {
      if (q >= trips) break;
      ulonglong2 X = rq[q],      Y  = rq[8 + q];   // LDS.128 broadcast
      ulonglong2 Z = rq[16 + q], Wv = rq[24 + q];

      u64 s01 = fmul2(pA0, X.x);  s01 = ffma2(pB0, Y.x, s01);
      u64 s23 = fmul2(pA0, X.y);  s23 = ffma2(pB0, Y.y, s23);
      u64 r01 = fmul2(pA1, X.x);  r01 = ffma2(pB1, Y.x, r01);
      u64 r23 = fmul2(pA1, X.y);  r23 = ffma2(pB1, Y.y, r23);
      s01 = ffma2(pC0, Z.x, s01); s01 = ffma2(pD0, Wv.x, s01);
      s23 = ffma2(pC0, Z.y, s23); s23 = ffma2(pD0, Wv.y, s23);
      r01 = ffma2(pC1, Z.x, r01); r01 = ffma2(pD1, Wv.x, r01);
      r23 = ffma2(pC1, Z.y, r23); r23 = ffma2(pD1, Wv.y, r23);

      // 4 FMNMX per channel per quad (register-pair alias unpacks).
      m0 = fmaxf(m0, fmaxf(fmaxf(lo2(s01), hi2(s01)),
                           fmaxf(lo2(s23), hi2(s23))));
      m1 = fmaxf(m1, fmaxf(fmaxf(lo2(r01), hi2(r01)),
                           fmaxf(lo2(r23), hi2(r23))));
    }

    // Scalar per-pillar bias chains (5 FFMA each, no packing movs).
    float rn = __fdividef(1.0f, (float)np);
    float mx = lo2(sxy) * rn, my = hi2(sxy) * rn, mz = sz * rn;
    float cx = fmaf((float)cyx.y, 0.16f, 0.08f);
    float cy = fmaf((float)cyx.x, 0.16f, -39.6f);
    float bias0 = fmaf(mz, n8a, fmaf(my, n7a, fmaf(mx, n6a,
                  fmaf(cy, n5a, fmaf(cx, n4a, bb0)))));
    float bias1 = fmaf(mz, n8b, fmaf(my, n7b, fmaf(mx, n6b,
                  fmaf(cy, n5b, fmaf(cx, n4b, bb1)))));

    // Epilogue: bias, relu floor (incl. masked-point bn contribution), store.
    float g0 = (np < 32) ? rbb0 : 0.0f;
    float g1 = (np < 32) ? rbb1 : 0.0f;
    float2 res = make_float2(fmaxf(m0 + bias0, g0), fmaxf(m1 + bias1, g1));
    reinterpret_cast<float2*>(out)[(size_t)p * 32 + lane] = res;  // ch (2l,2l+1)

    if (!more) break;
    v = vN; np = npN; cyx = cyxN; p = pn;
    bufoff ^= 128;
  }
}

extern "C" void kernel_launch(void* const* d_in, const int* in_sizes, int n_in,
                              void* d_out, int out_size) {
  const float4* voxels = (const float4*)d_in[0];
  const float*  W      = (const float*)d_in[1];
  const float*  gamma  = (const float*)d_in[2];
  const float*  beta   = (const float*)d_in[3];
  const float*  rmean  = (const float*)d_in[4];
  const float*  rvar   = (const float*)d_in[5];
  const int*    vnum   = (const int*)d_in[6];
  const int*    vcrd   = (const int*)d_in[7];
  float* out = (float*)d_out;

  int P = in_sizes[6];
  int needed = (P + NWARP - 1) / NWARP;
  int blocks = needed < GRID_BLOCKS ? needed : GRID_BLOCKS;
  pillar_vfe_kernel<<<blocks, 256>>>(voxels, W, gamma, beta, rmean, rvar,
                                     vnum, vcrd, out, P);
}